// round 16
// baseline (speedup 1.0000x reference)
#include <cuda_runtime.h>
#include <cuda_fp16.h>
#include <cstdint>

#define D_MODEL 1024
#define N_HEADS 16
#define D_K     64
#define SEQ     2048
#define BSZ     2
#define M_TOK   (BSZ * SEQ)   // 4096 tokens

// ---------------------------------------------------------------------------
// fp16 arena (device global: allocation-free rule).
// ---------------------------------------------------------------------------
#define MEG (1048576ULL)
__device__ __half g_hf[40 * MEG];

static const size_t OFF_IQH = 0;
static const size_t OFF_IKH = 4 * MEG;
static const size_t OFF_IVH = 8 * MEG;
static const size_t OFF_WQH = 12 * MEG;
static const size_t OFF_WKH = 13 * MEG;
static const size_t OFF_WVH = 14 * MEG;
static const size_t OFF_WOH = 15 * MEG;
static const size_t OFF_PQH = 16 * MEG;
static const size_t OFF_PKH = 20 * MEG;
static const size_t OFF_PVH = 24 * MEG;
static const size_t OFF_OH  = 28 * MEG;

// ---------------------------------------------------------------------------
// PTX wrappers (baseline PTX — compiles at compute_103)
// ---------------------------------------------------------------------------
__device__ __forceinline__ uint32_t smem_u32(const void* p) {
    uint32_t a;
    asm("{ .reg .u64 t; cvta.to.shared.u64 t, %1; cvt.u32.u64 %0, t; }"
        : "=r"(a) : "l"(p));
    return a;
}
__device__ __forceinline__ void ldsm_x4(uint32_t* r, uint32_t addr) {
    asm volatile("ldmatrix.sync.aligned.m8n8.x4.shared.b16 {%0,%1,%2,%3}, [%4];"
                 : "=r"(r[0]), "=r"(r[1]), "=r"(r[2]), "=r"(r[3]) : "r"(addr));
}
__device__ __forceinline__ void ldsm_x4_t(uint32_t* r, uint32_t addr) {
    asm volatile("ldmatrix.sync.aligned.m8n8.x4.trans.shared.b16 {%0,%1,%2,%3}, [%4];"
                 : "=r"(r[0]), "=r"(r[1]), "=r"(r[2]), "=r"(r[3]) : "r"(addr));
}
__device__ __forceinline__ void mma16816(float* d, const uint32_t* a, const uint32_t* b) {
    asm volatile(
        "mma.sync.aligned.m16n8k16.row.col.f32.f16.f16.f32 "
        "{%0,%1,%2,%3}, {%4,%5,%6,%7}, {%8,%9}, {%0,%1,%2,%3};"
        : "+f"(d[0]), "+f"(d[1]), "+f"(d[2]), "+f"(d[3])
        : "r"(a[0]), "r"(a[1]), "r"(a[2]), "r"(a[3]), "r"(b[0]), "r"(b[1]));
}
__device__ __forceinline__ void cp16(uint32_t saddr, const void* g) {
    asm volatile("cp.async.cg.shared.global [%0], [%1], 16;"
                 :: "r"(saddr), "l"(g));
}
#define CP_COMMIT() asm volatile("cp.async.commit_group;" ::: "memory")
#define CP_WAIT1()  asm volatile("cp.async.wait_group 1;" ::: "memory")
#define CP_WAIT0()  asm volatile("cp.async.wait_group 0;" ::: "memory")

// ---------------------------------------------------------------------------
// Fused convert: all 7 tensors fp32 -> fp16 in ONE launch.
// ---------------------------------------------------------------------------
struct SplitArgs {
    const float* src[7];
    __half* hi[7];
};

__global__ __launch_bounds__(256)
void split_all(SplitArgs a)
{
    int blk = blockIdx.x;
    int seg, rel;
    if (blk < 12288) { seg = blk >> 12; rel = blk & 4095; }
    else             { seg = 3 + ((blk - 12288) >> 10); rel = (blk - 12288) & 1023; }
    int i = rel * 256 + threadIdx.x;

    float4 v = ((const float4*)a.src[seg])[i];
    __half2 ph0; ph0.x = __float2half_rn(v.x); ph0.y = __float2half_rn(v.y);
    __half2 ph1; ph1.x = __float2half_rn(v.z); ph1.y = __float2half_rn(v.w);
    ((__half2*)a.hi[seg])[i * 2 + 0] = ph0;
    ((__half2*)a.hi[seg])[i * 2 + 1] = ph1;
}

// ---------------------------------------------------------------------------
// Tensor-core fp16 GEMM: C = A*B^T (+bias)*scale, fp32 accumulation.
// CTA 128(M) x 256(N), BK=32, 256 threads, warp tile 64x64.
// 3-stage cp.async pipeline; fragment loads interleaved under MMA shadows;
// precomputed offsets + rotating stage pointers.
// ---------------------------------------------------------------------------
#define SP 40                         // smem row stride in halves (80B = 5x16B)
#define A_TSZB (128 * SP * 2)         // 10240
#define B_TSZB (256 * SP * 2)         // 20480
#define STGB (A_TSZB + B_TSZB)        // 30720
#define GSMEM (3 * STGB)              // 92160

struct GemmOne {
    const __half* Ah;
    const __half* Bh;
    const float* bias;
    __half* Ch;
    float* C;
    float scale;
};
struct GemmQKV { GemmOne g[3]; };

template<int MODE>
__device__ __forceinline__ void gemm_core(const GemmOne& P, int bm, int bn)
{
    extern __shared__ __align__(16) char dsm[];
    const uint32_t base = smem_u32(dsm);
    const int tid  = threadIdx.x;
    const int wid  = tid >> 5;
    const int lane = tid & 31;
    const int wm = (wid >> 2) * 64;
    const int wn = (wid & 3) * 64;

    float acc[4][8][4];
#pragma unroll
    for (int i = 0; i < 4; i++)
#pragma unroll
        for (int j = 0; j < 8; j++)
#pragma unroll
            for (int r = 0; r < 4; r++) acc[i][j][r] = 0.f;

    const int arow = lane & 15;
    const int acol = (lane >> 4) * 8;
    const int b4row = (lane >> 4) * 8 + (lane & 7);
    const int b4col = ((lane >> 3) & 1) * 8;

    // Precomputed fragment byte offsets (ks stride = 16 halves = 32 B)
    uint32_t aoff[4], boff[4];
#pragma unroll
    for (int mt = 0; mt < 4; mt++)
        aoff[mt] = (uint32_t)((wm + mt * 16 + arow) * SP + acol) * 2;
#pragma unroll
    for (int p = 0; p < 4; p++)
        boff[p] = (uint32_t)(A_TSZB) + (uint32_t)((wn + p * 16 + b4row) * SP + b4col) * 2;

    auto load_stage = [&](uint32_t sb, int k0) {
#pragma unroll
        for (int j = 0; j < 2; j++) {
            int c    = tid + j * 256;
            int row  = c >> 2;
            int kcol = (c & 3) * 8;
            size_t ga = (size_t)(bm + row) * D_MODEL + k0 + kcol;
            uint32_t so = (uint32_t)(row * SP + kcol) * 2;
            cp16(sb + so, &P.Ah[ga]);
        }
#pragma unroll
        for (int j = 0; j < 4; j++) {
            int c    = tid + j * 256;
            int row  = c >> 2;
            int kcol = (c & 3) * 8;
            size_t gb = (size_t)(bn + row) * D_MODEL + k0 + kcol;
            uint32_t so = (uint32_t)(row * SP + kcol) * 2;
            cp16(sb + A_TSZB + so, &P.Bh[gb]);
        }
    };

    const uint32_t end3 = base + 3 * STGB;
    uint32_t cbase = base;              // compute stage ptr
    uint32_t lbase = base + 2 * STGB;   // next load stage ptr

    load_stage(base, 0);         CP_COMMIT();
    load_stage(base + STGB, 32); CP_COMMIT();

    for (int kc = 0; kc < 32; kc++) {
        if (kc < 31) CP_WAIT1(); else CP_WAIT0();
        __syncthreads();
        if (kc < 30) {
            load_stage(lbase, (kc + 2) * 32);
            CP_COMMIT();
            lbase += STGB; if (lbase == end3) lbase = base;
        }

#pragma unroll
        for (int ks = 0; ks < 2; ks++) {
            const uint32_t kso = ks * 32;   // bytes
            uint32_t bh[8][2];
#pragma unroll
            for (int p = 0; p < 4; p++)
                ldsm_x4(&bh[2 * p][0], cbase + boff[p] + kso);
            uint32_t ah[4][4];
            ldsm_x4(ah[0], cbase + aoff[0] + kso);
#pragma unroll
            for (int mt = 0; mt < 4; mt++) {
                if (mt < 3) ldsm_x4(ah[mt + 1], cbase + aoff[mt + 1] + kso);
#pragma unroll
                for (int nt = 0; nt < 8; nt++)
                    mma16816(acc[mt][nt], ah[mt], bh[nt]);
            }
        }
        cbase += STGB; if (cbase == end3) cbase = base;
    }

#pragma unroll
    for (int mt = 0; mt < 4; mt++) {
#pragma unroll
        for (int half = 0; half < 2; half++) {
            int m = bm + wm + mt * 16 + (lane >> 2) + half * 8;
            int b = m >> 11, s = m & 2047;
#pragma unroll
            for (int nt = 0; nt < 8; nt++) {
                int n = bn + wn + nt * 8 + 2 * (lane & 3);
                float vx = (acc[mt][nt][half * 2 + 0] + P.bias[n + 0]) * P.scale;
                float vy = (acc[mt][nt][half * 2 + 1] + P.bias[n + 1]) * P.scale;
                if (MODE == 1) {
                    int h = n >> 6, dd = n & 63;
                    size_t co = ((size_t)(b * N_HEADS + h) * SEQ + s) * D_K + dd;
                    __half2 hh;
                    hh.x = __float2half_rn(vx); hh.y = __float2half_rn(vy);
                    *(__half2*)&P.Ch[co] = hh;
                } else {
                    float2 v; v.x = vx; v.y = vy;
                    *(float2*)&P.C[(size_t)m * D_MODEL + n] = v;
                }
            }
        }
    }
}

__global__ __launch_bounds__(256)
void gemm_qkv(GemmQKV P)
{
    gemm_core<1>(P.g[blockIdx.z], blockIdx.y * 128, blockIdx.x * 256);
}

__global__ __launch_bounds__(256)
void gemm_o(GemmOne P)
{
    gemm_core<0>(P, blockIdx.y * 128, blockIdx.x * 256);
}

// ---------------------------------------------------------------------------
// Flash attention: fp16 operands, fp32 accumulation.
// 128 threads, 32 q-rows/warp (128/CTA), Q register-resident, KV tiles 64.
// 3-stage cp.async; loads interleaved under MMA shadows; correction-skip.
// ---------------------------------------------------------------------------
#define ST 72
#define FTSZB (64 * ST * 2)          // 9216
#define FSTGB (2 * FTSZB)            // Kh, Vh  (18432)
#define QTSZB (128 * ST * 2)         // 18432
#define QOFF  (3 * FSTGB)
#define FSMEM (3 * FSTGB + QTSZB)    // 73728

__global__ __launch_bounds__(128)
void flash_mma(const __half* __restrict__ Qh,
               const __half* __restrict__ Kh, const __half* __restrict__ Vh,
               __half* __restrict__ Oh)
{
    extern __shared__ __align__(16) char fsm[];
    const uint32_t base = smem_u32(fsm);

    const int bh  = blockIdx.y;
    const int q0  = blockIdx.x * 128;
    const int tid = threadIdx.x;
    const int w   = tid >> 5;
    const int lane = tid & 31;
    const size_t bhoff = (size_t)bh * SEQ * D_K;

    // ---- stage Q (128 rows), extract register-resident A-fragments ----
    {
        __half* sQh = (__half*)(fsm + QOFF);
#pragma unroll
        for (int it = 0; it < 8; it++) {
            int idx = tid + it * 128;
            int row = idx >> 3, c8 = (idx & 7) * 8;
            size_t g = bhoff + (size_t)(q0 + row) * D_K + c8;
            *(uint4*)&sQh[row * ST + c8] = *(const uint4*)&Qh[g];
        }
    }
    __syncthreads();
    uint32_t qh[2][4][4];
    {
        const uint32_t uQh = base + QOFF;
        const int arow = lane & 15, acol = (lane >> 4) * 8;
#pragma unroll
        for (int mt = 0; mt < 2; mt++)
#pragma unroll
            for (int ks = 0; ks < 4; ks++) {
                uint32_t off = ((w * 32 + mt * 16 + arow) * ST + ks * 16 + acol) * 2;
                ldsm_x4(qh[mt][ks], uQh + off);
            }
    }

    auto load_kv = [&](uint32_t sb, int kv0) {
#pragma unroll
        for (int it = 0; it < 4; it++) {
            int idx = tid + it * 128;
            int row = idx >> 3, c8 = (idx & 7) * 8;
            size_t g = bhoff + (size_t)(kv0 + row) * D_K + c8;
            uint32_t so = (uint32_t)(row * ST + c8) * 2;
            cp16(sb + 0 * FTSZB + so, &Kh[g]);
            cp16(sb + 1 * FTSZB + so, &Vh[g]);
        }
    };

    float o[2][8][4];
#pragma unroll
    for (int mt = 0; mt < 2; mt++)
#pragma unroll
        for (int i = 0; i < 8; i++)
#pragma unroll
            for (int r = 0; r < 4; r++) o[mt][i][r] = 0.f;
    float mA[2] = { -1e30f, -1e30f }, mB[2] = { -1e30f, -1e30f };
    float lA[2] = { 0.f, 0.f },       lB[2] = { 0.f, 0.f };

    const uint32_t fend3 = base + 3 * FSTGB;
    uint32_t cbase = base;
    uint32_t lbase = base + 2 * FSTGB;

    load_kv(base, 0);          CP_COMMIT();
    load_kv(base + FSTGB, 64); CP_COMMIT();

    // precomputed fragment base offsets
    const int b4row = (lane >> 4) * 8 + (lane & 7);
    const int b4col = ((lane >> 3) & 1) * 8;
    uint32_t kbase[4], vbase[4];
#pragma unroll
    for (int p = 0; p < 4; p++) {
        kbase[p] = (uint32_t)((p * 16 + b4row) * ST + b4col) * 2;
        vbase[p] = (uint32_t)(FTSZB) +
                   (uint32_t)(((lane & 15)) * ST + (2 * p + (lane >> 4)) * 8) * 2;
    }
    // per-ks strides: K += 32 B (16 halves); V += 16 rows * ST halves * 2 B
    const uint32_t VKS = (uint32_t)(16 * ST) * 2;

    const int NT = SEQ / 64;   // 32
    for (int t = 0; t < NT; t++) {
        if (t < NT - 1) CP_WAIT1(); else CP_WAIT0();
        __syncthreads();
        if (t < NT - 2) {
            load_kv(lbase, (t + 2) * 64);
            CP_COMMIT();
            lbase += FSTGB; if (lbase == fend3) lbase = base;
        }

        // ---- S = Qh . Kh ----
        float s[2][8][4];
#pragma unroll
        for (int mt = 0; mt < 2; mt++)
#pragma unroll
            for (int i = 0; i < 8; i++)
#pragma unroll
                for (int r = 0; r < 4; r++) s[mt][i][r] = 0.f;

#pragma unroll
        for (int ks = 0; ks < 4; ks++) {
            const uint32_t kso = ks * 32;
            uint32_t kk[8][2];
            ldsm_x4(&kk[0][0], cbase + kbase[0] + kso);
#pragma unroll
            for (int p = 0; p < 4; p++) {
                if (p < 3) ldsm_x4(&kk[2 * (p + 1)][0], cbase + kbase[p + 1] + kso);
#pragma unroll
                for (int mt = 0; mt < 2; mt++) {
                    mma16816(s[mt][2 * p + 0], qh[mt][ks], kk[2 * p + 0]);
                    mma16816(s[mt][2 * p + 1], qh[mt][ks], kk[2 * p + 1]);
                }
            }
        }

        // ---- online softmax update (per m-tile, correction-skip) ----
        float mnA[2], mnB[2];
#pragma unroll
        for (int mt = 0; mt < 2; mt++) {
            float tA = -1e30f, tB = -1e30f;
#pragma unroll
            for (int nt = 0; nt < 8; nt++) {
                tA = fmaxf(tA, fmaxf(s[mt][nt][0], s[mt][nt][1]));
                tB = fmaxf(tB, fmaxf(s[mt][nt][2], s[mt][nt][3]));
            }
            tA = fmaxf(tA, __shfl_xor_sync(0xffffffff, tA, 1));
            tA = fmaxf(tA, __shfl_xor_sync(0xffffffff, tA, 2));
            tB = fmaxf(tB, __shfl_xor_sync(0xffffffff, tB, 1));
            tB = fmaxf(tB, __shfl_xor_sync(0xffffffff, tB, 2));
            mnA[mt] = fmaxf(mA[mt], tA);
            mnB[mt] = fmaxf(mB[mt], tB);
            // warp-uniform skip: rescale only if a max actually moved
            if (mnA[mt] > mA[mt] || mnB[mt] > mB[mt]) {
                float cA = exp2f(mA[mt] - mnA[mt]);
                float cB = exp2f(mB[mt] - mnB[mt]);
                lA[mt] *= cA; lB[mt] *= cB;
#pragma unroll
                for (int nt = 0; nt < 8; nt++) {
                    o[mt][nt][0] *= cA; o[mt][nt][1] *= cA;
                    o[mt][nt][2] *= cB; o[mt][nt][3] *= cB;
                }
                mA[mt] = mnA[mt]; mB[mt] = mnB[mt];
            }
        }

        // ---- O += P . Vh, P converted per kv-slice, V loads under MMA ----
#pragma unroll
        for (int ks = 0; ks < 4; ks++) {
            const uint32_t vso = ks * VKS;
            uint32_t vv[8][2];
#pragma unroll
            for (int p = 0; p < 4; p++)
                ldsm_x4_t(&vv[2 * p][0], cbase + vbase[p] + vso);
            uint32_t aPh[2][4];
#pragma unroll
            for (int mt = 0; mt < 2; mt++) {
#pragma unroll
                for (int h16 = 0; h16 < 2; h16++) {
                    int nt = 2 * ks + h16;
                    float p0 = exp2f(s[mt][nt][0] - mnA[mt]);
                    float p1 = exp2f(s[mt][nt][1] - mnA[mt]);
                    float p2 = exp2f(s[mt][nt][2] - mnB[mt]);
                    float p3 = exp2f(s[mt][nt][3] - mnB[mt]);
                    lA[mt] += p0 + p1; lB[mt] += p2 + p3;
                    __half2 tt;
                    tt.x = __float2half_rn(p0); tt.y = __float2half_rn(p1);
                    aPh[mt][h16 * 2 + 0] = *(uint32_t*)&tt;
                    tt.x = __float2half_rn(p2); tt.y = __float2half_rn(p3);
                    aPh[mt][h16 * 2 + 1] = *(uint32_t*)&tt;
                }
            }
#pragma unroll
            for (int mt = 0; mt < 2; mt++)
#pragma unroll
                for (int ntd = 0; ntd < 8; ntd++)
                    mma16816(o[mt][ntd], aPh[mt], vv[ntd]);
        }
        cbase += FSTGB; if (cbase == fend3) cbase = base;
    }

    // ---- finalize ----
    const int b = bh >> 4, h = bh & 15;
    const int c2 = 2 * (lane & 3);
#pragma unroll
    for (int mt = 0; mt < 2; mt++) {
        float la = lA[mt], lb = lB[mt];
        la += __shfl_xor_sync(0xffffffff, la, 1);
        la += __shfl_xor_sync(0xffffffff, la, 2);
        lb += __shfl_xor_sync(0xffffffff, lb, 1);
        lb += __shfl_xor_sync(0xffffffff, lb, 2);
        float invA = 1.f / la, invB = 1.f / lb;
        int rowA = q0 + w * 32 + mt * 16 + (lane >> 2);
        int rowB = rowA + 8;
#pragma unroll
        for (int ntd = 0; ntd < 8; ntd++) {
            float v0 = o[mt][ntd][0] * invA, v1 = o[mt][ntd][1] * invA;
            float v2 = o[mt][ntd][2] * invB, v3 = o[mt][ntd][3] * invB;
            size_t offA = (size_t)(b * SEQ + rowA) * D_MODEL + h * D_K + ntd * 8 + c2;
            size_t offB = (size_t)(b * SEQ + rowB) * D_MODEL + h * D_K + ntd * 8 + c2;
            __half2 t2;
            t2.x = __float2half_rn(v0); t2.y = __float2half_rn(v1);
            *(__half2*)&Oh[offA] = t2;
            t2.x = __float2half_rn(v2); t2.y = __float2half_rn(v3);
            *(__half2*)&Oh[offB] = t2;
        }
    }
}

// ---------------------------------------------------------------------------
// Launch
// ---------------------------------------------------------------------------
extern "C" void kernel_launch(void* const* d_in, const int* in_sizes, int n_in,
                              void* d_out, int out_size)
{
    const float* q   = (const float*)d_in[0];
    const float* k   = (const float*)d_in[1];
    const float* v   = (const float*)d_in[2];
    const float* W_q = (const float*)d_in[3];
    const float* b_q = (const float*)d_in[4];
    const float* W_k = (const float*)d_in[5];
    const float* b_k = (const float*)d_in[6];
    const float* W_v = (const float*)d_in[7];
    const float* b_v = (const float*)d_in[8];
    const float* W_o = (const float*)d_in[9];
    const float* b_o = (const float*)d_in[10];
    float* out = (float*)d_out;

    __half* hf;
    cudaGetSymbolAddress((void**)&hf, g_hf);

    cudaFuncSetAttribute((void*)gemm_qkv, cudaFuncAttributeMaxDynamicSharedMemorySize, GSMEM);
    cudaFuncSetAttribute((void*)gemm_o,   cudaFuncAttributeMaxDynamicSharedMemorySize, GSMEM);
    cudaFuncSetAttribute((void*)flash_mma, cudaFuncAttributeMaxDynamicSharedMemorySize, FSMEM);

    SplitArgs sa;
    sa.src[0] = q;   sa.hi[0] = hf + OFF_IQH;
    sa.src[1] = k;   sa.hi[1] = hf + OFF_IKH;
    sa.src[2] = v;   sa.hi[2] = hf + OFF_IVH;
    sa.src[3] = W_q; sa.hi[3] = hf + OFF_WQH;
    sa.src[4] = W_k; sa.hi[4] = hf + OFF_WKH;
    sa.src[5] = W_v; sa.hi[5] = hf + OFF_WVH;
    sa.src[6] = W_o; sa.hi[6] = hf + OFF_WOH;
    split_all<<<16384, 256>>>(sa);

    const float qscale = 0.125f * 1.4426950408889634f;
    GemmQKV gp;
    gp.g[0] = { hf + OFF_IQH, hf + OFF_WQH, b_q, hf + OFF_PQH, nullptr, qscale };
    gp.g[1] = { hf + OFF_IKH, hf + OFF_WKH, b_k, hf + OFF_PKH, nullptr, 1.0f };
    gp.g[2] = { hf + OFF_IVH, hf + OFF_WVH, b_v, hf + OFF_PVH, nullptr, 1.0f };
    dim3 ggrid(D_MODEL / 256, M_TOK / 128, 3);   // (4, 32, 3) = 384 CTAs
    gemm_qkv<<<ggrid, 256, GSMEM>>>(gp);

    dim3 agrid(SEQ / 128, BSZ * N_HEADS);        // (16, 32) = 512 CTAs
    flash_mma<<<agrid, 128, FSMEM>>>(hf + OFF_PQH,
                                     hf + OFF_PKH, hf + OFF_PVH,
                                     hf + OFF_OH);

    GemmOne go = { hf + OFF_OH, hf + OFF_WOH, b_o, nullptr, out, 1.0f };
    dim3 ogrid(D_MODEL / 256, M_TOK / 128);      // (4, 32) = 128 CTAs
    gemm_o<<<ogrid, 256, GSMEM>>>(go);
}

// round 17
// speedup vs baseline: 1.0674x; 1.0674x over previous
#include <cuda_runtime.h>
#include <cuda_fp16.h>
#include <cstdint>

#define D_MODEL 1024
#define N_HEADS 16
#define D_K     64
#define SEQ     2048
#define BSZ     2
#define M_TOK   (BSZ * SEQ)   // 4096 tokens

// ---------------------------------------------------------------------------
// fp16 arena (device global: allocation-free rule).
// ---------------------------------------------------------------------------
#define MEG (1048576ULL)
__device__ __half g_hf[40 * MEG];

static const size_t OFF_IQH = 0;
static const size_t OFF_IKH = 4 * MEG;
static const size_t OFF_IVH = 8 * MEG;
static const size_t OFF_WQH = 12 * MEG;
static const size_t OFF_WKH = 13 * MEG;
static const size_t OFF_WVH = 14 * MEG;
static const size_t OFF_WOH = 15 * MEG;
static const size_t OFF_PQH = 16 * MEG;
static const size_t OFF_PKH = 20 * MEG;
static const size_t OFF_PVH = 24 * MEG;
static const size_t OFF_OH  = 28 * MEG;

// ---------------------------------------------------------------------------
// PTX wrappers (baseline PTX — compiles at compute_103)
// ---------------------------------------------------------------------------
__device__ __forceinline__ uint32_t smem_u32(const void* p) {
    uint32_t a;
    asm("{ .reg .u64 t; cvta.to.shared.u64 t, %1; cvt.u32.u64 %0, t; }"
        : "=r"(a) : "l"(p));
    return a;
}
__device__ __forceinline__ void ldsm_x4(uint32_t* r, uint32_t addr) {
    asm volatile("ldmatrix.sync.aligned.m8n8.x4.shared.b16 {%0,%1,%2,%3}, [%4];"
                 : "=r"(r[0]), "=r"(r[1]), "=r"(r[2]), "=r"(r[3]) : "r"(addr));
}
__device__ __forceinline__ void ldsm_x4_t(uint32_t* r, uint32_t addr) {
    asm volatile("ldmatrix.sync.aligned.m8n8.x4.trans.shared.b16 {%0,%1,%2,%3}, [%4];"
                 : "=r"(r[0]), "=r"(r[1]), "=r"(r[2]), "=r"(r[3]) : "r"(addr));
}
__device__ __forceinline__ void mma16816(float* d, const uint32_t* a, const uint32_t* b) {
    asm volatile(
        "mma.sync.aligned.m16n8k16.row.col.f32.f16.f16.f32 "
        "{%0,%1,%2,%3}, {%4,%5,%6,%7}, {%8,%9}, {%0,%1,%2,%3};"
        : "+f"(d[0]), "+f"(d[1]), "+f"(d[2]), "+f"(d[3])
        : "r"(a[0]), "r"(a[1]), "r"(a[2]), "r"(a[3]), "r"(b[0]), "r"(b[1]));
}
__device__ __forceinline__ void cp16(uint32_t saddr, const void* g) {
    asm volatile("cp.async.cg.shared.global [%0], [%1], 16;"
                 :: "r"(saddr), "l"(g));
}
#define CP_COMMIT() asm volatile("cp.async.commit_group;" ::: "memory")
#define CP_WAIT1()  asm volatile("cp.async.wait_group 1;" ::: "memory")
#define CP_WAIT0()  asm volatile("cp.async.wait_group 0;" ::: "memory")

// ---------------------------------------------------------------------------
// Fused convert: all 7 tensors fp32 -> fp16 in ONE launch.
// ---------------------------------------------------------------------------
struct SplitArgs {
    const float* src[7];
    __half* hi[7];
};

__global__ __launch_bounds__(256)
void split_all(SplitArgs a)
{
    int blk = blockIdx.x;
    int seg, rel;
    if (blk < 12288) { seg = blk >> 12; rel = blk & 4095; }
    else             { seg = 3 + ((blk - 12288) >> 10); rel = (blk - 12288) & 1023; }
    int i = rel * 256 + threadIdx.x;

    float4 v = ((const float4*)a.src[seg])[i];
    __half2 ph0; ph0.x = __float2half_rn(v.x); ph0.y = __float2half_rn(v.y);
    __half2 ph1; ph1.x = __float2half_rn(v.z); ph1.y = __float2half_rn(v.w);
    ((__half2*)a.hi[seg])[i * 2 + 0] = ph0;
    ((__half2*)a.hi[seg])[i * 2 + 1] = ph1;
}

// ---------------------------------------------------------------------------
// Tensor-core fp16 GEMM: C = A*B^T (+bias)*scale, fp32 accumulation.
// CTA 128(M) x 256(N), BK=64 (16 kc-iterations), 256 threads, warp tile 64x64.
// 3-stage cp.async pipeline, x4-merged B fragment loads.
// ---------------------------------------------------------------------------
#define SP 72                         // smem row stride in halves (144B = 9x16B)
#define A_TSZB (128 * SP * 2)         // 18432
#define B_TSZB (256 * SP * 2)         // 36864
#define STGB (A_TSZB + B_TSZB)        // 55296
#define GSMEM (3 * STGB)              // 165888

struct GemmOne {
    const __half* Ah;
    const __half* Bh;
    const float* bias;
    __half* Ch;
    float* C;
    float scale;
};
struct GemmQKV { GemmOne g[3]; };

template<int MODE>
__device__ __forceinline__ void gemm_core(const GemmOne& P, int bm, int bn)
{
    extern __shared__ __align__(16) char dsm[];
    const uint32_t base = smem_u32(dsm);
    const int tid  = threadIdx.x;
    const int wid  = tid >> 5;
    const int lane = tid & 31;
    const int wm = (wid >> 2) * 64;
    const int wn = (wid & 3) * 64;

    float acc[4][8][4];
#pragma unroll
    for (int i = 0; i < 4; i++)
#pragma unroll
        for (int j = 0; j < 8; j++)
#pragma unroll
            for (int r = 0; r < 4; r++) acc[i][j][r] = 0.f;

    const int arow = lane & 15;
    const int acol = (lane >> 4) * 8;
    const int b4row = (lane >> 4) * 8 + (lane & 7);
    const int b4col = ((lane >> 3) & 1) * 8;

    // Precomputed fragment byte offsets (ks stride = 16 halves = 32 B)
    uint32_t aoff[4], boff[4];
#pragma unroll
    for (int mt = 0; mt < 4; mt++)
        aoff[mt] = (uint32_t)((wm + mt * 16 + arow) * SP + acol) * 2;
#pragma unroll
    for (int p = 0; p < 4; p++)
        boff[p] = (uint32_t)(A_TSZB) + (uint32_t)((wn + p * 16 + b4row) * SP + b4col) * 2;

    // BK=64: A = 128 rows x 8 chunks (1024), B = 256 rows x 8 chunks (2048)
    auto load_stage = [&](uint32_t sb, int k0) {
#pragma unroll
        for (int j = 0; j < 4; j++) {
            int c    = tid + j * 256;
            int row  = c >> 3;
            int kcol = (c & 7) * 8;
            size_t ga = (size_t)(bm + row) * D_MODEL + k0 + kcol;
            uint32_t so = (uint32_t)(row * SP + kcol) * 2;
            cp16(sb + so, &P.Ah[ga]);
        }
#pragma unroll
        for (int j = 0; j < 8; j++) {
            int c    = tid + j * 256;
            int row  = c >> 3;
            int kcol = (c & 7) * 8;
            size_t gb = (size_t)(bn + row) * D_MODEL + k0 + kcol;
            uint32_t so = (uint32_t)(row * SP + kcol) * 2;
            cp16(sb + A_TSZB + so, &P.Bh[gb]);
        }
    };

    const uint32_t end3 = base + 3 * STGB;
    uint32_t cbase = base;
    uint32_t lbase = base + 2 * STGB;

    load_stage(base, 0);         CP_COMMIT();
    load_stage(base + STGB, 64); CP_COMMIT();

    for (int kc = 0; kc < 16; kc++) {
        if (kc < 15) CP_WAIT1(); else CP_WAIT0();
        __syncthreads();
        if (kc < 14) {
            load_stage(lbase, (kc + 2) * 64);
            CP_COMMIT();
            lbase += STGB; if (lbase == end3) lbase = base;
        }

#pragma unroll
        for (int ks = 0; ks < 4; ks++) {
            const uint32_t kso = ks * 32;   // bytes
            uint32_t bh[8][2];
#pragma unroll
            for (int p = 0; p < 4; p++)
                ldsm_x4(&bh[2 * p][0], cbase + boff[p] + kso);
            uint32_t ah[4][4];
            ldsm_x4(ah[0], cbase + aoff[0] + kso);
#pragma unroll
            for (int mt = 0; mt < 4; mt++) {
                if (mt < 3) ldsm_x4(ah[mt + 1], cbase + aoff[mt + 1] + kso);
#pragma unroll
                for (int nt = 0; nt < 8; nt++)
                    mma16816(acc[mt][nt], ah[mt], bh[nt]);
            }
        }
        cbase += STGB; if (cbase == end3) cbase = base;
    }

#pragma unroll
    for (int mt = 0; mt < 4; mt++) {
#pragma unroll
        for (int half = 0; half < 2; half++) {
            int m = bm + wm + mt * 16 + (lane >> 2) + half * 8;
            int b = m >> 11, s = m & 2047;
#pragma unroll
            for (int nt = 0; nt < 8; nt++) {
                int n = bn + wn + nt * 8 + 2 * (lane & 3);
                float vx = (acc[mt][nt][half * 2 + 0] + P.bias[n + 0]) * P.scale;
                float vy = (acc[mt][nt][half * 2 + 1] + P.bias[n + 1]) * P.scale;
                if (MODE == 1) {
                    int h = n >> 6, dd = n & 63;
                    size_t co = ((size_t)(b * N_HEADS + h) * SEQ + s) * D_K + dd;
                    __half2 hh;
                    hh.x = __float2half_rn(vx); hh.y = __float2half_rn(vy);
                    *(__half2*)&P.Ch[co] = hh;
                } else {
                    float2 v; v.x = vx; v.y = vy;
                    *(float2*)&P.C[(size_t)m * D_MODEL + n] = v;
                }
            }
        }
    }
}

__global__ __launch_bounds__(256)
void gemm_qkv(GemmQKV P)
{
    gemm_core<1>(P.g[blockIdx.z], blockIdx.y * 128, blockIdx.x * 256);
}

__global__ __launch_bounds__(256)
void gemm_o(GemmOne P)
{
    gemm_core<0>(P, blockIdx.y * 128, blockIdx.x * 256);
}

// ---------------------------------------------------------------------------
// Flash attention (unchanged from R16): fp16 operands, fp32 accumulation.
// 128 threads, 32 q-rows/warp, Q register-resident, KV tiles 64, 3-stage.
// ---------------------------------------------------------------------------
#define ST 72
#define FTSZB (64 * ST * 2)          // 9216
#define FSTGB (2 * FTSZB)            // Kh, Vh  (18432)
#define QTSZB (128 * ST * 2)         // 18432
#define QOFF  (3 * FSTGB)
#define FSMEM (3 * FSTGB + QTSZB)    // 73728

__global__ __launch_bounds__(128)
void flash_mma(const __half* __restrict__ Qh,
               const __half* __restrict__ Kh, const __half* __restrict__ Vh,
               __half* __restrict__ Oh)
{
    extern __shared__ __align__(16) char fsm[];
    const uint32_t base = smem_u32(fsm);

    const int bh  = blockIdx.y;
    const int q0  = blockIdx.x * 128;
    const int tid = threadIdx.x;
    const int w   = tid >> 5;
    const int lane = tid & 31;
    const size_t bhoff = (size_t)bh * SEQ * D_K;

    {
        __half* sQh = (__half*)(fsm + QOFF);
#pragma unroll
        for (int it = 0; it < 8; it++) {
            int idx = tid + it * 128;
            int row = idx >> 3, c8 = (idx & 7) * 8;
            size_t g = bhoff + (size_t)(q0 + row) * D_K + c8;
            *(uint4*)&sQh[row * ST + c8] = *(const uint4*)&Qh[g];
        }
    }
    __syncthreads();
    uint32_t qh[2][4][4];
    {
        const uint32_t uQh = base + QOFF;
        const int arow = lane & 15, acol = (lane >> 4) * 8;
#pragma unroll
        for (int mt = 0; mt < 2; mt++)
#pragma unroll
            for (int ks = 0; ks < 4; ks++) {
                uint32_t off = ((w * 32 + mt * 16 + arow) * ST + ks * 16 + acol) * 2;
                ldsm_x4(qh[mt][ks], uQh + off);
            }
    }

    auto load_kv = [&](uint32_t sb, int kv0) {
#pragma unroll
        for (int it = 0; it < 4; it++) {
            int idx = tid + it * 128;
            int row = idx >> 3, c8 = (idx & 7) * 8;
            size_t g = bhoff + (size_t)(kv0 + row) * D_K + c8;
            uint32_t so = (uint32_t)(row * ST + c8) * 2;
            cp16(sb + 0 * FTSZB + so, &Kh[g]);
            cp16(sb + 1 * FTSZB + so, &Vh[g]);
        }
    };

    float o[2][8][4];
#pragma unroll
    for (int mt = 0; mt < 2; mt++)
#pragma unroll
        for (int i = 0; i < 8; i++)
#pragma unroll
            for (int r = 0; r < 4; r++) o[mt][i][r] = 0.f;
    float mA[2] = { -1e30f, -1e30f }, mB[2] = { -1e30f, -1e30f };
    float lA[2] = { 0.f, 0.f },       lB[2] = { 0.f, 0.f };

    const uint32_t fend3 = base + 3 * FSTGB;
    uint32_t cbase = base;
    uint32_t lbase = base + 2 * FSTGB;

    load_kv(base, 0);          CP_COMMIT();
    load_kv(base + FSTGB, 64); CP_COMMIT();

    const int b4row = (lane >> 4) * 8 + (lane & 7);
    const int b4col = ((lane >> 3) & 1) * 8;
    uint32_t kbase[4], vbase[4];
#pragma unroll
    for (int p = 0; p < 4; p++) {
        kbase[p] = (uint32_t)((p * 16 + b4row) * ST + b4col) * 2;
        vbase[p] = (uint32_t)(FTSZB) +
                   (uint32_t)(((lane & 15)) * ST + (2 * p + (lane >> 4)) * 8) * 2;
    }
    const uint32_t VKS = (uint32_t)(16 * ST) * 2;

    const int NT = SEQ / 64;   // 32
    for (int t = 0; t < NT; t++) {
        if (t < NT - 1) CP_WAIT1(); else CP_WAIT0();
        __syncthreads();
        if (t < NT - 2) {
            load_kv(lbase, (t + 2) * 64);
            CP_COMMIT();
            lbase += FSTGB; if (lbase == fend3) lbase = base;
        }

        float s[2][8][4];
#pragma unroll
        for (int mt = 0; mt < 2; mt++)
#pragma unroll
            for (int i = 0; i < 8; i++)
#pragma unroll
                for (int r = 0; r < 4; r++) s[mt][i][r] = 0.f;

#pragma unroll
        for (int ks = 0; ks < 4; ks++) {
            const uint32_t kso = ks * 32;
            uint32_t kk[8][2];
            ldsm_x4(&kk[0][0], cbase + kbase[0] + kso);
#pragma unroll
            for (int p = 0; p < 4; p++) {
                if (p < 3) ldsm_x4(&kk[2 * (p + 1)][0], cbase + kbase[p + 1] + kso);
#pragma unroll
                for (int mt = 0; mt < 2; mt++) {
                    mma16816(s[mt][2 * p + 0], qh[mt][ks], kk[2 * p + 0]);
                    mma16816(s[mt][2 * p + 1], qh[mt][ks], kk[2 * p + 1]);
                }
            }
        }

        float mnA[2], mnB[2];
#pragma unroll
        for (int mt = 0; mt < 2; mt++) {
            float tA = -1e30f, tB = -1e30f;
#pragma unroll
            for (int nt = 0; nt < 8; nt++) {
                tA = fmaxf(tA, fmaxf(s[mt][nt][0], s[mt][nt][1]));
                tB = fmaxf(tB, fmaxf(s[mt][nt][2], s[mt][nt][3]));
            }
            tA = fmaxf(tA, __shfl_xor_sync(0xffffffff, tA, 1));
            tA = fmaxf(tA, __shfl_xor_sync(0xffffffff, tA, 2));
            tB = fmaxf(tB, __shfl_xor_sync(0xffffffff, tB, 1));
            tB = fmaxf(tB, __shfl_xor_sync(0xffffffff, tB, 2));
            mnA[mt] = fmaxf(mA[mt], tA);
            mnB[mt] = fmaxf(mB[mt], tB);
            if (mnA[mt] > mA[mt] || mnB[mt] > mB[mt]) {
                float cA = exp2f(mA[mt] - mnA[mt]);
                float cB = exp2f(mB[mt] - mnB[mt]);
                lA[mt] *= cA; lB[mt] *= cB;
#pragma unroll
                for (int nt = 0; nt < 8; nt++) {
                    o[mt][nt][0] *= cA; o[mt][nt][1] *= cA;
                    o[mt][nt][2] *= cB; o[mt][nt][3] *= cB;
                }
                mA[mt] = mnA[mt]; mB[mt] = mnB[mt];
            }
        }

#pragma unroll
        for (int ks = 0; ks < 4; ks++) {
            const uint32_t vso = ks * VKS;
            uint32_t vv[8][2];
#pragma unroll
            for (int p = 0; p < 4; p++)
                ldsm_x4_t(&vv[2 * p][0], cbase + vbase[p] + vso);
            uint32_t aPh[2][4];
#pragma unroll
            for (int mt = 0; mt < 2; mt++) {
#pragma unroll
                for (int h16 = 0; h16 < 2; h16++) {
                    int nt = 2 * ks + h16;
                    float p0 = exp2f(s[mt][nt][0] - mnA[mt]);
                    float p1 = exp2f(s[mt][nt][1] - mnA[mt]);
                    float p2 = exp2f(s[mt][nt][2] - mnB[mt]);
                    float p3 = exp2f(s[mt][nt][3] - mnB[mt]);
                    lA[mt] += p0 + p1; lB[mt] += p2 + p3;
                    __half2 tt;
                    tt.x = __float2half_rn(p0); tt.y = __float2half_rn(p1);
                    aPh[mt][h16 * 2 + 0] = *(uint32_t*)&tt;
                    tt.x = __float2half_rn(p2); tt.y = __float2half_rn(p3);
                    aPh[mt][h16 * 2 + 1] = *(uint32_t*)&tt;
                }
            }
#pragma unroll
            for (int mt = 0; mt < 2; mt++)
#pragma unroll
                for (int ntd = 0; ntd < 8; ntd++)
                    mma16816(o[mt][ntd], aPh[mt], vv[ntd]);
        }
        cbase += FSTGB; if (cbase == fend3) cbase = base;
    }

    const int b = bh >> 4, h = bh & 15;
    const int c2 = 2 * (lane & 3);
#pragma unroll
    for (int mt = 0; mt < 2; mt++) {
        float la = lA[mt], lb = lB[mt];
        la += __shfl_xor_sync(0xffffffff, la, 1);
        la += __shfl_xor_sync(0xffffffff, la, 2);
        lb += __shfl_xor_sync(0xffffffff, lb, 1);
        lb += __shfl_xor_sync(0xffffffff, lb, 2);
        float invA = 1.f / la, invB = 1.f / lb;
        int rowA = q0 + w * 32 + mt * 16 + (lane >> 2);
        int rowB = rowA + 8;
#pragma unroll
        for (int ntd = 0; ntd < 8; ntd++) {
            float v0 = o[mt][ntd][0] * invA, v1 = o[mt][ntd][1] * invA;
            float v2 = o[mt][ntd][2] * invB, v3 = o[mt][ntd][3] * invB;
            size_t offA = (size_t)(b * SEQ + rowA) * D_MODEL + h * D_K + ntd * 8 + c2;
            size_t offB = (size_t)(b * SEQ + rowB) * D_MODEL + h * D_K + ntd * 8 + c2;
            __half2 t2;
            t2.x = __float2half_rn(v0); t2.y = __float2half_rn(v1);
            *(__half2*)&Oh[offA] = t2;
            t2.x = __float2half_rn(v2); t2.y = __float2half_rn(v3);
            *(__half2*)&Oh[offB] = t2;
        }
    }
}

// ---------------------------------------------------------------------------
// Launch
// ---------------------------------------------------------------------------
extern "C" void kernel_launch(void* const* d_in, const int* in_sizes, int n_in,
                              void* d_out, int out_size)
{
    const float* q   = (const float*)d_in[0];
    const float* k   = (const float*)d_in[1];
    const float* v   = (const float*)d_in[2];
    const float* W_q = (const float*)d_in[3];
    const float* b_q = (const float*)d_in[4];
    const float* W_k = (const float*)d_in[5];
    const float* b_k = (const float*)d_in[6];
    const float* W_v = (const float*)d_in[7];
    const float* b_v = (const float*)d_in[8];
    const float* W_o = (const float*)d_in[9];
    const float* b_o = (const float*)d_in[10];
    float* out = (float*)d_out;

    __half* hf;
    cudaGetSymbolAddress((void**)&hf, g_hf);

    cudaFuncSetAttribute((void*)gemm_qkv, cudaFuncAttributeMaxDynamicSharedMemorySize, GSMEM);
    cudaFuncSetAttribute((void*)gemm_o,   cudaFuncAttributeMaxDynamicSharedMemorySize, GSMEM);
    cudaFuncSetAttribute((void*)flash_mma, cudaFuncAttributeMaxDynamicSharedMemorySize, FSMEM);

    SplitArgs sa;
    sa.src[0] = q;   sa.hi[0] = hf + OFF_IQH;
    sa.src[1] = k;   sa.hi[1] = hf + OFF_IKH;
    sa.src[2] = v;   sa.hi[2] = hf + OFF_IVH;
    sa.src[3] = W_q; sa.hi[3] = hf + OFF_WQH;
    sa.src[4] = W_k; sa.hi[4] = hf + OFF_WKH;
    sa.src[5] = W_v; sa.hi[5] = hf + OFF_WVH;
    sa.src[6] = W_o; sa.hi[6] = hf + OFF_WOH;
    split_all<<<16384, 256>>>(sa);

    const float qscale = 0.125f * 1.4426950408889634f;
    GemmQKV gp;
    gp.g[0] = { hf + OFF_IQH, hf + OFF_WQH, b_q, hf + OFF_PQH, nullptr, qscale };
    gp.g[1] = { hf + OFF_IKH, hf + OFF_WKH, b_k, hf + OFF_PKH, nullptr, 1.0f };
    gp.g[2] = { hf + OFF_IVH, hf + OFF_WVH, b_v, hf + OFF_PVH, nullptr, 1.0f };
    dim3 ggrid(D_MODEL / 256, M_TOK / 128, 3);   // (4, 32, 3) = 384 CTAs
    gemm_qkv<<<ggrid, 256, GSMEM>>>(gp);

    dim3 agrid(SEQ / 128, BSZ * N_HEADS);        // (16, 32) = 512 CTAs
    flash_mma<<<agrid, 128, FSMEM>>>(hf + OFF_PQH,
                                     hf + OFF_PKH, hf + OFF_PVH,
                                     hf + OFF_OH);

    GemmOne go = { hf + OFF_OH, hf + OFF_WOH, b_o, nullptr, out, 1.0f };
    dim3 ogrid(D_MODEL / 256, M_TOK / 128);      // (4, 32) = 128 CTAs
    gemm_o<<<ogrid, 256, GSMEM>>>(go);
}